// round 7
// baseline (speedup 1.0000x reference)
#include <cuda_runtime.h>

#define NMAX 50000
#define EMAX 800000
#define RR 3
#define HH 64
#define CC 5
#define N3MAX (NMAX * RR)
#define RPB 64            // rows per block in layer kernel
#define LTHREADS 256

// ---------------- device scratch (total ~19 MB, far below 62 MiB limit) ----------------
__device__ __align__(16) float g_h1[(size_t)NMAX * HH];
__device__ int   g_cnt[N3MAX];
__device__ int   g_cur[N3MAX];
__device__ int   g_offs[N3MAX + 1];
__device__ int   g_bsum[256];
__device__ float g_inv[N3MAX];
__device__ int   g_esrc[EMAX];
__device__ int   g_is64;

// ---------------- index helpers (int64 vs int32 tolerant) ----------------
__device__ __forceinline__ int load_idx(const void* p, long long i) {
    if (g_is64) return (int)((const long long*)p)[i];
    return ((const int*)p)[i];
}

// ---------------- init: zero counters + width detection (block 0) ----------------
__global__ void init_k(const int* __restrict__ w, int e, int n3) {
    int i = blockIdx.x * blockDim.x + threadIdx.x;
    if (i < n3) { g_cnt[i] = 0; g_cur[i] = 0; }
    if (blockIdx.x == 0) {
        __shared__ int nz;
        if (threadIdx.x == 0) nz = 0;
        __syncthreads();
        int npairs = e < 1024 ? e : 1024;
        int local = 0;
        for (int j = threadIdx.x; j < npairs; j += blockDim.x)
            if (w[2 * j + 1] != 0) local = 1;
        if (local) atomicExch(&nz, 1);
        __syncthreads();
        if (threadIdx.x == 0) g_is64 = (nz == 0) ? 1 : 0;
    }
}

__global__ void count_k(const void* __restrict__ ei, const void* __restrict__ et, int e) {
    int i = blockIdx.x * blockDim.x + threadIdx.x;
    if (i < e) {
        int dst = load_idx(ei, (long long)e + i);
        int r   = load_idx(et, i);
        atomicAdd(&g_cnt[dst * RR + r], 1);
    }
}

// scan pass 1 (+ fused reciprocal of counts)
__global__ __launch_bounds__(1024) void scan1_k(int n3) {
    __shared__ int sh[1024];
    int tid = threadIdx.x;
    int gi = blockIdx.x * 1024 + tid;
    int v = (gi < n3) ? g_cnt[gi] : 0;
    if (gi < n3) g_inv[gi] = 1.0f / (float)(v > 0 ? v : 1);
    sh[tid] = v;
    __syncthreads();
    for (int off = 1; off < 1024; off <<= 1) {
        int t = (tid >= off) ? sh[tid - off] : 0;
        __syncthreads();
        sh[tid] += t;
        __syncthreads();
    }
    if (gi < n3) g_offs[gi] = sh[tid] - v;   // exclusive
    if (tid == 1023) g_bsum[blockIdx.x] = sh[1023];
}

__global__ void scan2_k(int nb) {
    if (threadIdx.x == 0 && blockIdx.x == 0) {
        int run = 0;
        for (int b = 0; b < nb; b++) { int t = g_bsum[b]; g_bsum[b] = run; run += t; }
    }
}

__global__ void scan3_k(int n3, int e) {
    int gi = blockIdx.x * blockDim.x + threadIdx.x;
    if (gi < n3) g_offs[gi] += g_bsum[gi >> 10];
    else if (gi == n3) g_offs[n3] = e;
}

__global__ void fill_k(const void* __restrict__ ei, const void* __restrict__ et, int e) {
    int i = blockIdx.x * blockDim.x + threadIdx.x;
    if (i < e) {
        int src = load_idx(ei, i);
        int dst = load_idx(ei, (long long)e + i);
        int r   = load_idx(et, i);
        int w = dst * RR + r;
        int pos = g_offs[w] + atomicAdd(&g_cur[w], 1);
        g_esrc[pos] = src;
    }
}

// ---------------- packed f32x2 helpers (value semantics only) ----------------
__device__ __forceinline__ unsigned long long pack2(float x) {
    unsigned long long r;
    asm("mov.b64 %0, {%1, %1};" : "=l"(r) : "f"(x));
    return r;
}
__device__ __forceinline__ unsigned long long pack2two(float x, float y) {
    unsigned long long r;
    asm("mov.b64 %0, {%1, %2};" : "=l"(r) : "f"(x), "f"(y));
    return r;
}
__device__ __forceinline__ unsigned long long ffma2(unsigned long long a,
                                                    unsigned long long b,
                                                    unsigned long long c) {
    unsigned long long d;
    asm("fma.rn.f32x2 %0, %1, %2, %3;" : "=l"(d) : "l"(a), "l"(b), "l"(c));
    return d;
}
__device__ __forceinline__ float2 unpack2(unsigned long long v) {
    float2 f;
    asm("mov.b64 {%0, %1}, %2;" : "=f"(f.x), "=f"(f.y) : "l"(v));
    return f;
}

// ---------------- fused layer: gather-mean (smem) + GEMM + bias + relu [+ head] ----
// Block: 64 rows, 256 threads. Dynamic smem: sAgg[3*64*64] + Ws[64*64] = 64 KB.
// Phase A: warp per (row,rel) segment -> mean into smem.
// Phase B: 4 threads per row, 16 output cols each; weights broadcast from smem.
// layer==1: out = relu(...) -> g_h1.  layer==2: fused head -> logits (h2 never stored).
__global__ __launch_bounds__(LTHREADS) void layer_k(
    const float* __restrict__ x,
    const float* __restrict__ Wrel,
    const float* __restrict__ root,
    const float* __restrict__ bias,
    const float* __restrict__ Wc,
    const float* __restrict__ bc,
    float* __restrict__ outHead,
    int n, int layer)
{
    extern __shared__ float sm[];
    float* sAgg = sm;                       // [RR][RPB][HH]
    float* Ws   = sm + RR * RPB * HH;       // [HH][HH]

    int tid = threadIdx.x;
    int rowbase = blockIdx.x * RPB;
    const float* xin = (layer == 1) ? x : g_h1;

    // ---------- Phase A: gather means into smem ----------
    {
        int wid = tid >> 5, lane = tid & 31;
        for (int seg = wid; seg < RR * RPB; seg += (LTHREADS / 32)) {
            int lr = seg / RR, r = seg - lr * RR;
            int row = rowbase + lr;
            float a0 = 0.f, a1 = 0.f, b0 = 0.f, b1 = 0.f;
            float sc = 0.f;
            if (row < n) {
                int w = row * RR + r;
                int s = g_offs[w], t = g_offs[w + 1];
                int i = s;
                for (; i + 1 < t; i += 2) {
                    const float* p0 = xin + (size_t)g_esrc[i] * HH;
                    const float* p1 = xin + (size_t)g_esrc[i + 1] * HH;
                    a0 += p0[lane]; a1 += p0[lane + 32];
                    b0 += p1[lane]; b1 += p1[lane + 32];
                }
                if (i < t) {
                    const float* p0 = xin + (size_t)g_esrc[i] * HH;
                    a0 += p0[lane]; a1 += p0[lane + 32];
                }
                sc = g_inv[w];
            }
            float* o = sAgg + (r * RPB + lr) * HH;
            o[lane]      = (a0 + b0) * sc;
            o[lane + 32] = (a1 + b1) * sc;
        }
    }
    __syncthreads();

    // ---------- Phase B: GEMM ----------
    int lr  = tid >> 2;     // local row 0..63
    int cg  = tid & 3;      // column group: cols [cg*16, cg*16+16)
    int row = rowbase + lr;
    int crow = row < n ? row : 0;

    unsigned long long acc[8];
    {
        const float2* b2 = (const float2*)(bias + cg * 16);
        #pragma unroll
        for (int j = 0; j < 8; j++) { float2 b = b2[j]; acc[j] = pack2two(b.x, b.y); }
    }

    for (int m = 0; m < 4; m++) {
        const float* W = (m == 0) ? root : (Wrel + (size_t)(m - 1) * HH * HH);
        __syncthreads();
        {
            const float4* w4 = (const float4*)W;
            float4* s4 = (float4*)Ws;
            for (int i = tid; i < HH * HH / 4; i += LTHREADS) s4[i] = w4[i];
        }
        __syncthreads();

        const float* src = (m == 0) ? (xin + (size_t)crow * HH)
                                    : (sAgg + ((m - 1) * RPB + lr) * HH);

        #pragma unroll 4
        for (int k4 = 0; k4 < 16; k4++) {
            float4 v = ((const float4*)src)[k4];
            #define GSTEP(E, KK)                                                            \
            {                                                                               \
                unsigned long long p = pack2(E);                                            \
                const ulonglong2* wr = (const ulonglong2*)&Ws[(4 * k4 + KK) * HH + cg * 16];\
                _Pragma("unroll")                                                           \
                for (int j = 0; j < 4; j++) {                                               \
                    ulonglong2 w2 = wr[j];                                                  \
                    acc[2 * j]     = ffma2(p, w2.x, acc[2 * j]);                            \
                    acc[2 * j + 1] = ffma2(p, w2.y, acc[2 * j + 1]);                        \
                }                                                                           \
            }
            GSTEP(v.x, 0)
            GSTEP(v.y, 1)
            GSTEP(v.z, 2)
            GSTEP(v.w, 3)
            #undef GSTEP
        }
    }

    if (layer == 1) {
        if (row < n) {
            float4* o4 = (float4*)(g_h1 + (size_t)row * HH + cg * 16);
            #pragma unroll
            for (int j = 0; j < 4; j++) {
                float2 lo = unpack2(acc[2 * j]);
                float2 hi = unpack2(acc[2 * j + 1]);
                float a = lo.x > 0.f ? lo.x : 0.f;
                float b = lo.y > 0.f ? lo.y : 0.f;
                float c = hi.x > 0.f ? hi.x : 0.f;
                float d = hi.y > 0.f ? hi.y : 0.f;
                o4[j] = make_float4(a, b, c, d);
            }
        }
    } else {
        // fused head: partial logits from this thread's 16 h2 columns
        float p[CC];
        #pragma unroll
        for (int c = 0; c < CC; c++) p[c] = 0.f;
        #pragma unroll
        for (int j = 0; j < 8; j++) {
            float2 v = unpack2(acc[j]);
            float h0 = v.x > 0.f ? v.x : 0.f;
            float h1v = v.y > 0.f ? v.y : 0.f;
            int k0 = cg * 16 + 2 * j;
            #pragma unroll
            for (int c = 0; c < CC; c++)
                p[c] += h0 * __ldg(&Wc[k0 * CC + c]) + h1v * __ldg(&Wc[(k0 + 1) * CC + c]);
        }
        #pragma unroll
        for (int c = 0; c < CC; c++) {
            p[c] += __shfl_down_sync(0xffffffffu, p[c], 1, 4);
            p[c] += __shfl_down_sync(0xffffffffu, p[c], 2, 4);
        }
        if (cg == 0 && row < n) {
            #pragma unroll
            for (int c = 0; c < CC; c++)
                outHead[(size_t)row * CC + c] = p[c] + __ldg(&bc[c]);
        }
    }
}

// ---------------- launch ----------------
extern "C" void kernel_launch(void* const* d_in, const int* in_sizes, int n_in,
                              void* d_out, int out_size)
{
    const float* x     = (const float*)d_in[0];
    const float* W1    = (const float*)d_in[1];
    const float* root1 = (const float*)d_in[2];
    const float* b1    = (const float*)d_in[3];
    const float* W2    = (const float*)d_in[4];
    const float* root2 = (const float*)d_in[5];
    const float* b2    = (const float*)d_in[6];
    const float* Wc    = (const float*)d_in[7];
    const float* bc    = (const float*)d_in[8];
    const void*  ei    = d_in[9];
    const void*  et    = d_in[10];
    float* out = (float*)d_out;

    int n  = in_sizes[0] / HH;     // 50000
    int e  = in_sizes[10];         // 800000
    int n3 = n * RR;
    int nb = (n3 + 1023) / 1024;

    const int smemBytes = (RR * RPB * HH + HH * HH) * (int)sizeof(float);  // 64 KB
    static int attrSet = 0;
    if (!attrSet) {
        cudaFuncSetAttribute(layer_k, cudaFuncAttributeMaxDynamicSharedMemorySize, smemBytes);
        attrSet = 1;
    }

    // CSR build (6 launches)
    init_k<<<(n3 + 255) / 256, 256>>>((const int*)ei, e, n3);
    count_k<<<(e + 255) / 256, 256>>>(ei, et, e);
    scan1_k<<<nb, 1024>>>(n3);
    scan2_k<<<1, 32>>>(nb);
    scan3_k<<<(n3 + 1 + 255) / 256, 256>>>(n3, e);
    fill_k<<<(e + 255) / 256, 256>>>(ei, et, e);

    int gBlocks = (n + RPB - 1) / RPB;

    // layer 1: fused gather + GEMM + relu -> g_h1
    layer_k<<<gBlocks, LTHREADS, smemBytes>>>(x, W1, root1, b1, Wc, bc, out, n, 1);
    // layer 2: fused gather + GEMM + relu + classifier head -> out
    layer_k<<<gBlocks, LTHREADS, smemBytes>>>(x, W2, root2, b2, Wc, bc, out, n, 2);
}

// round 8
// speedup vs baseline: 2.3114x; 2.3114x over previous
#include <cuda_runtime.h>

#define NMAX 50000
#define EMAX 800000
#define RR 3
#define HH 64
#define CC 5
#define N3MAX (NMAX * RR)
#define SLICE ((size_t)NMAX * HH)

// ---------------- device scratch (keep total < 62 MiB) ----------------
// slices 0..2: per-relation agg means; slice 3: h1
__device__ __align__(16) float g_pool[4 * SLICE];
__device__ int   g_cnt[N3MAX];
__device__ int   g_cur[N3MAX];
__device__ int   g_offs[N3MAX + 1];
__device__ int   g_bsum[256];
__device__ float g_inv[N3MAX];
__device__ int   g_esrc[EMAX];
__device__ int   g_is64;

// ---------------- index helpers ----------------
__device__ __forceinline__ int load_idx(const void* p, long long i) {
    if (g_is64) return (int)((const long long*)p)[i];
    return ((const int*)p)[i];
}

// ---------------- init: zero counters + int64/int32 detection ----------------
__global__ void init_k(const int* __restrict__ w, int e, int n3) {
    int i = blockIdx.x * blockDim.x + threadIdx.x;
    if (i < n3) { g_cnt[i] = 0; g_cur[i] = 0; }
    if (blockIdx.x == 0) {
        __shared__ int nz;
        if (threadIdx.x == 0) nz = 0;
        __syncthreads();
        int npairs = e < 1024 ? e : 1024;
        int local = 0;
        for (int j = threadIdx.x; j < npairs; j += blockDim.x)
            if (w[2 * j + 1] != 0) local = 1;
        if (local) atomicExch(&nz, 1);
        __syncthreads();
        if (threadIdx.x == 0) g_is64 = (nz == 0) ? 1 : 0;
    }
}

__global__ void count_k(const void* __restrict__ ei, const void* __restrict__ et, int e) {
    int i = blockIdx.x * blockDim.x + threadIdx.x;
    if (i < e) {
        int dst = load_idx(ei, (long long)e + i);
        int r   = load_idx(et, i);
        atomicAdd(&g_cnt[dst * RR + r], 1);
    }
}

// scan pass 1 (+ fused reciprocal)
__global__ __launch_bounds__(1024) void scan1_k(int n3) {
    __shared__ int sh[1024];
    int tid = threadIdx.x;
    int gi = blockIdx.x * 1024 + tid;
    int v = (gi < n3) ? g_cnt[gi] : 0;
    if (gi < n3) g_inv[gi] = 1.0f / (float)(v > 0 ? v : 1);
    sh[tid] = v;
    __syncthreads();
    for (int off = 1; off < 1024; off <<= 1) {
        int t = (tid >= off) ? sh[tid - off] : 0;
        __syncthreads();
        sh[tid] += t;
        __syncthreads();
    }
    if (gi < n3) g_offs[gi] = sh[tid] - v;   // exclusive
    if (tid == 1023) g_bsum[blockIdx.x] = sh[1023];
}

// pass 2: PARALLEL scan of block sums (one block, shared memory)
__global__ __launch_bounds__(256) void scan2_k(int nb) {
    __shared__ int sh[256];
    int tid = threadIdx.x;
    int v = (tid < nb) ? g_bsum[tid] : 0;
    sh[tid] = v;
    __syncthreads();
    for (int off = 1; off < 256; off <<= 1) {
        int t = (tid >= off) ? sh[tid - off] : 0;
        __syncthreads();
        sh[tid] += t;
        __syncthreads();
    }
    if (tid < nb) g_bsum[tid] = sh[tid] - v;  // exclusive
}

__global__ void scan3_k(int n3, int e) {
    int gi = blockIdx.x * blockDim.x + threadIdx.x;
    if (gi < n3) g_offs[gi] += g_bsum[gi >> 10];
    else if (gi == n3) g_offs[n3] = e;
}

__global__ void fill_k(const void* __restrict__ ei, const void* __restrict__ et, int e) {
    int i = blockIdx.x * blockDim.x + threadIdx.x;
    if (i < e) {
        int src = load_idx(ei, i);
        int dst = load_idx(ei, (long long)e + i);
        int r   = load_idx(et, i);
        int w = dst * RR + r;
        int pos = g_offs[w] + atomicAdd(&g_cur[w], 1);
        g_esrc[pos] = src;
    }
}

// ---------------- atomic-free aggregation: warp per (dst, rel) segment, 4-way MLP ----
__global__ void agg_k(const float* __restrict__ x, int n, int layer) {
    int gt = blockIdx.x * blockDim.x + threadIdx.x;
    int w = gt >> 5;
    int lane = gt & 31;
    int n3 = n * RR;
    if (w >= n3) return;

    const float* xin = (layer == 1) ? x : (g_pool + 3 * SLICE);

    int s = g_offs[w], t = g_offs[w + 1];
    float a0 = 0.f, a1 = 0.f, b0 = 0.f, b1 = 0.f;
    float c0 = 0.f, c1 = 0.f, d0 = 0.f, d1 = 0.f;
    int i = s;
    for (; i + 3 < t; i += 4) {
        const float* p0 = xin + (size_t)__ldg(&g_esrc[i])     * HH;
        const float* p1 = xin + (size_t)__ldg(&g_esrc[i + 1]) * HH;
        const float* p2 = xin + (size_t)__ldg(&g_esrc[i + 2]) * HH;
        const float* p3 = xin + (size_t)__ldg(&g_esrc[i + 3]) * HH;
        a0 += __ldg(&p0[lane]); a1 += __ldg(&p0[lane + 32]);
        b0 += __ldg(&p1[lane]); b1 += __ldg(&p1[lane + 32]);
        c0 += __ldg(&p2[lane]); c1 += __ldg(&p2[lane + 32]);
        d0 += __ldg(&p3[lane]); d1 += __ldg(&p3[lane + 32]);
    }
    if (i + 1 < t) {
        const float* p0 = xin + (size_t)__ldg(&g_esrc[i])     * HH;
        const float* p1 = xin + (size_t)__ldg(&g_esrc[i + 1]) * HH;
        a0 += __ldg(&p0[lane]); a1 += __ldg(&p0[lane + 32]);
        b0 += __ldg(&p1[lane]); b1 += __ldg(&p1[lane + 32]);
        i += 2;
    }
    if (i < t) {
        const float* p0 = xin + (size_t)__ldg(&g_esrc[i]) * HH;
        c0 += __ldg(&p0[lane]); c1 += __ldg(&p0[lane + 32]);
    }
    float sc = g_inv[w];
    int r = w % RR, dst = w / RR;
    float* o = g_pool + (size_t)r * SLICE + (size_t)dst * HH;
    o[lane]      = ((a0 + b0) + (c0 + d0)) * sc;
    o[lane + 32] = ((a1 + b1) + (c1 + d1)) * sc;
}

// ---------------- packed f32x2 helpers (value semantics only) ----------------
__device__ __forceinline__ unsigned long long pack2(float x) {
    unsigned long long r;
    asm("mov.b64 %0, {%1, %1};" : "=l"(r) : "f"(x));
    return r;
}
__device__ __forceinline__ unsigned long long pack2two(float x, float y) {
    unsigned long long r;
    asm("mov.b64 %0, {%1, %2};" : "=l"(r) : "f"(x), "f"(y));
    return r;
}
__device__ __forceinline__ unsigned long long ffma2(unsigned long long a,
                                                    unsigned long long b,
                                                    unsigned long long c) {
    unsigned long long d;
    asm("fma.rn.f32x2 %0, %1, %2, %3;" : "=l"(d) : "l"(a), "l"(b), "l"(c));
    return d;
}
__device__ __forceinline__ float2 unpack2(unsigned long long v) {
    float2 f;
    asm("mov.b64 {%0, %1}, %2;" : "=f"(f.x), "=f"(f.y) : "l"(v));
    return f;
}

// ---------------- fused layer GEMM (+head on layer 2) ----------------
// 128 threads/block, one row per thread, f32x2 packed accumulators.
// layer==1: h1 = relu(x@root + sum_r agg[r]@W[r] + b) -> pool slice 3
// layer==2: logits = relu(...) @ Wc + bc -> out   (h2 never materialized)
__global__ __launch_bounds__(128) void rgcn_gemm_k(
    const float* __restrict__ x,
    const float* __restrict__ Wrel,
    const float* __restrict__ root,
    const float* __restrict__ bias,
    const float* __restrict__ Wc,
    const float* __restrict__ bc,
    float* __restrict__ outHead,
    int n, int layer)
{
    __shared__ __align__(16) float Ws[HH * HH];
    __shared__ float Wcs[HH * CC];
    __shared__ float bcs[CC];
    int tid = threadIdx.x;
    int row = blockIdx.x * 128 + tid;
    int crow = row < n ? row : 0;

    if (layer == 2) {
        for (int i = tid; i < HH * CC; i += 128) Wcs[i] = Wc[i];
        if (tid < CC) bcs[tid] = bc[tid];
    }

    unsigned long long acc[32];
    {
        const float2* b2 = (const float2*)bias;
        #pragma unroll
        for (int j = 0; j < 32; j++) { float2 b = b2[j]; acc[j] = pack2two(b.x, b.y); }
    }

    const float* xin = (layer == 1) ? x : (g_pool + 3 * SLICE);

    for (int m = 0; m < 4; m++) {
        const float* W = (m == 0) ? root : (Wrel + (size_t)(m - 1) * HH * HH);
        __syncthreads();
        {
            const float4* w4 = (const float4*)W;
            float4* s4 = (float4*)Ws;
            for (int i = tid; i < HH * HH / 4; i += 128) s4[i] = w4[i];
        }
        __syncthreads();

        const float* in = (m == 0) ? xin : (g_pool + (size_t)(m - 1) * SLICE);
        const float4* x4 = (const float4*)(in + (size_t)crow * HH);

        #pragma unroll 4
        for (int k4 = 0; k4 < 16; k4++) {
            float4 v = x4[k4];
            #define GSTEP(E, KK)                                                   \
            {                                                                      \
                unsigned long long p = pack2(E);                                   \
                const ulonglong2* wr = (const ulonglong2*)&Ws[(4 * k4 + KK) * HH]; \
                _Pragma("unroll")                                                  \
                for (int j = 0; j < 16; j++) {                                     \
                    ulonglong2 w2 = wr[j];                                         \
                    acc[2 * j]     = ffma2(p, w2.x, acc[2 * j]);                   \
                    acc[2 * j + 1] = ffma2(p, w2.y, acc[2 * j + 1]);               \
                }                                                                  \
            }
            GSTEP(v.x, 0)
            GSTEP(v.y, 1)
            GSTEP(v.z, 2)
            GSTEP(v.w, 3)
            #undef GSTEP
        }
    }

    if (layer == 1) {
        if (row < n) {
            float4* o4 = (float4*)(g_pool + 3 * SLICE + (size_t)row * HH);
            #pragma unroll
            for (int j = 0; j < 16; j++) {
                float2 lo = unpack2(acc[2 * j]);
                float2 hi = unpack2(acc[2 * j + 1]);
                float a = lo.x > 0.f ? lo.x : 0.f;
                float b = lo.y > 0.f ? lo.y : 0.f;
                float c = hi.x > 0.f ? hi.x : 0.f;
                float d = hi.y > 0.f ? hi.y : 0.f;
                o4[j] = make_float4(a, b, c, d);
            }
        }
    } else {
        // fused classifier head: logits = relu(h2) @ Wc + bc
        float p[CC];
        #pragma unroll
        for (int c = 0; c < CC; c++) p[c] = bcs[c];
        #pragma unroll
        for (int j = 0; j < 32; j++) {
            float2 v = unpack2(acc[j]);
            float h0 = v.x > 0.f ? v.x : 0.f;
            float h1 = v.y > 0.f ? v.y : 0.f;
            int k0 = 2 * j;
            #pragma unroll
            for (int c = 0; c < CC; c++)
                p[c] += h0 * Wcs[k0 * CC + c] + h1 * Wcs[(k0 + 1) * CC + c];
        }
        if (row < n) {
            #pragma unroll
            for (int c = 0; c < CC; c++)
                outHead[(size_t)row * CC + c] = p[c];
        }
    }
}

// ---------------- launch ----------------
extern "C" void kernel_launch(void* const* d_in, const int* in_sizes, int n_in,
                              void* d_out, int out_size)
{
    const float* x     = (const float*)d_in[0];
    const float* W1    = (const float*)d_in[1];
    const float* root1 = (const float*)d_in[2];
    const float* b1    = (const float*)d_in[3];
    const float* W2    = (const float*)d_in[4];
    const float* root2 = (const float*)d_in[5];
    const float* b2    = (const float*)d_in[6];
    const float* Wc    = (const float*)d_in[7];
    const float* bc    = (const float*)d_in[8];
    const void*  ei    = d_in[9];
    const void*  et    = d_in[10];
    float* out = (float*)d_out;

    int n  = in_sizes[0] / HH;     // 50000
    int e  = in_sizes[10];         // 800000
    int n3 = n * RR;
    int nb = (n3 + 1023) / 1024;   // 147

    // CSR build (6 launches)
    init_k<<<(n3 + 255) / 256, 256>>>((const int*)ei, e, n3);
    count_k<<<(e + 255) / 256, 256>>>(ei, et, e);
    scan1_k<<<nb, 1024>>>(n3);
    scan2_k<<<1, 256>>>(nb);
    scan3_k<<<(n3 + 1 + 255) / 256, 256>>>(n3, e);
    fill_k<<<(e + 255) / 256, 256>>>(ei, et, e);

    int aggBlocks  = (n3 * 32 + 255) / 256;
    int gemmBlocks = (n + 127) / 128;

    // layer 1
    agg_k<<<aggBlocks, 256>>>(x, n, 1);
    rgcn_gemm_k<<<gemmBlocks, 128>>>(x, W1, root1, b1, Wc, bc, out, n, 1);

    // layer 2 (head fused)
    agg_k<<<aggBlocks, 256>>>(x, n, 2);
    rgcn_gemm_k<<<gemmBlocks, 128>>>(x, W2, root2, b2, Wc, bc, out, n, 2);
}

// round 9
// speedup vs baseline: 2.3500x; 1.0167x over previous
#include <cuda_runtime.h>
#include <cooperative_groups.h>
namespace cg = cooperative_groups;

#define NMAX 50000
#define EMAX 800000
#define RR 3
#define HH 64
#define CC 5
#define N3MAX (NMAX * RR)
#define SLICE ((size_t)NMAX * HH)
#define CSR_BLOCKS 148
#define CSR_THREADS 1024

// ---------------- device scratch (keep total < 62 MiB) ----------------
// slices 0..2: per-relation agg means; slice 3: h1
__device__ __align__(16) float g_pool[4 * SLICE];
__device__ int   g_cnt[N3MAX];          // must be zero at kernel entry (module-load zero / self-cleaned)
__device__ int   g_cur[N3MAX];
__device__ int   g_offs[N3MAX + 1];
__device__ int   g_bsum[CSR_BLOCKS];
__device__ float g_inv[N3MAX];
__device__ int   g_esrc[EMAX];
__device__ int   g_is64;

// ---------------- index helpers ----------------
__device__ __forceinline__ int load_idx(const void* p, long long i) {
    if (g_is64) return (int)((const long long*)p)[i];
    return ((const int*)p)[i];
}

// ---------------- one cooperative kernel: detect + count + scan + fill ----------------
// grid = 148 blocks x 1024 threads (1 block/SM, co-resident).
// gridDim*blockDim = 151552 >= n3+1 = 150001 (one scan element per thread).
__global__ __launch_bounds__(CSR_THREADS) void csr_k(
    const int* __restrict__ w32,
    const void* __restrict__ ei,
    const void* __restrict__ et,
    int e, int n3)
{
    cg::grid_group grid = cg::this_grid();
    __shared__ int sh[CSR_THREADS];
    __shared__ int blockPrefix;
    __shared__ int nz;

    int tid = threadIdx.x;
    int bid = blockIdx.x;
    int gthreads = gridDim.x * blockDim.x;
    int gi = bid * CSR_THREADS + tid;

    // ---- phase 0: int64/int32 width detection (block 0) ----
    if (bid == 0) {
        if (tid == 0) nz = 0;
        __syncthreads();
        int npairs = e < 1024 ? e : 1024;
        int local = 0;
        for (int j = tid; j < npairs; j += CSR_THREADS)
            if (w32[2 * j + 1] != 0) local = 1;
        if (local) atomicExch(&nz, 1);
        __syncthreads();
        if (tid == 0) g_is64 = (nz == 0) ? 1 : 0;
    }
    grid.sync();

    // ---- phase 1: degree count (g_cnt is zero on entry) ----
    for (int i = gi; i < e; i += gthreads) {
        int dst = load_idx(ei, (long long)e + i);
        int r   = load_idx(et, i);
        atomicAdd(&g_cnt[dst * RR + r], 1);
    }
    grid.sync();

    // ---- phase 2: per-block scan, fused reciprocal, self-clean g_cnt ----
    int v = (gi < n3) ? g_cnt[gi] : 0;
    if (gi < n3) {
        g_inv[gi] = 1.0f / (float)(v > 0 ? v : 1);
        g_cnt[gi] = 0;                       // ready for next graph replay
    }
    sh[tid] = v;
    __syncthreads();
    for (int off = 1; off < CSR_THREADS; off <<= 1) {
        int t = (tid >= off) ? sh[tid - off] : 0;
        __syncthreads();
        sh[tid] += t;
        __syncthreads();
    }
    int incl = sh[tid];
    if (tid == CSR_THREADS - 1) g_bsum[bid] = incl;
    grid.sync();

    // ---- phase 3: add prefix of block sums; write offs and seed cur ----
    if (tid < 32) {
        int run = 0;
        for (int j = tid; j < bid; j += 32) run += g_bsum[j];
        #pragma unroll
        for (int o = 16; o > 0; o >>= 1)
            run += __shfl_down_sync(0xffffffffu, run, o);
        if (tid == 0) blockPrefix = run;
    }
    __syncthreads();
    int excl = blockPrefix + incl - v;
    if (gi < n3) { g_offs[gi] = excl; g_cur[gi] = excl; }
    if (gi == n3) g_offs[n3] = e;
    grid.sync();

    // ---- phase 4: fill (g_cur pre-seeded with offsets) ----
    for (int i = gi; i < e; i += gthreads) {
        int src = load_idx(ei, i);
        int dst = load_idx(ei, (long long)e + i);
        int r   = load_idx(et, i);
        int pos = atomicAdd(&g_cur[dst * RR + r], 1);
        g_esrc[pos] = src;
    }
}

// ---------------- atomic-free aggregation: warp per (dst, rel) segment, 4-way MLP ----
__global__ void agg_k(const float* __restrict__ x, int n, int layer) {
    int gt = blockIdx.x * blockDim.x + threadIdx.x;
    int w = gt >> 5;
    int lane = gt & 31;
    int n3 = n * RR;
    if (w >= n3) return;

    const float* xin = (layer == 1) ? x : (g_pool + 3 * SLICE);

    int s = g_offs[w], t = g_offs[w + 1];
    float a0 = 0.f, a1 = 0.f, b0 = 0.f, b1 = 0.f;
    float c0 = 0.f, c1 = 0.f, d0 = 0.f, d1 = 0.f;
    int i = s;
    for (; i + 3 < t; i += 4) {
        const float* p0 = xin + (size_t)__ldg(&g_esrc[i])     * HH;
        const float* p1 = xin + (size_t)__ldg(&g_esrc[i + 1]) * HH;
        const float* p2 = xin + (size_t)__ldg(&g_esrc[i + 2]) * HH;
        const float* p3 = xin + (size_t)__ldg(&g_esrc[i + 3]) * HH;
        a0 += __ldg(&p0[lane]); a1 += __ldg(&p0[lane + 32]);
        b0 += __ldg(&p1[lane]); b1 += __ldg(&p1[lane + 32]);
        c0 += __ldg(&p2[lane]); c1 += __ldg(&p2[lane + 32]);
        d0 += __ldg(&p3[lane]); d1 += __ldg(&p3[lane + 32]);
    }
    if (i + 1 < t) {
        const float* p0 = xin + (size_t)__ldg(&g_esrc[i])     * HH;
        const float* p1 = xin + (size_t)__ldg(&g_esrc[i + 1]) * HH;
        a0 += __ldg(&p0[lane]); a1 += __ldg(&p0[lane + 32]);
        b0 += __ldg(&p1[lane]); b1 += __ldg(&p1[lane + 32]);
        i += 2;
    }
    if (i < t) {
        const float* p0 = xin + (size_t)__ldg(&g_esrc[i]) * HH;
        c0 += __ldg(&p0[lane]); c1 += __ldg(&p0[lane + 32]);
    }
    float sc = g_inv[w];
    int r = w % RR, dst = w / RR;
    float* o = g_pool + (size_t)r * SLICE + (size_t)dst * HH;
    o[lane]      = ((a0 + b0) + (c0 + d0)) * sc;
    o[lane + 32] = ((a1 + b1) + (c1 + d1)) * sc;
}

// ---------------- packed f32x2 helpers (value semantics only) ----------------
__device__ __forceinline__ unsigned long long pack2(float x) {
    unsigned long long r;
    asm("mov.b64 %0, {%1, %1};" : "=l"(r) : "f"(x));
    return r;
}
__device__ __forceinline__ unsigned long long pack2two(float x, float y) {
    unsigned long long r;
    asm("mov.b64 %0, {%1, %2};" : "=l"(r) : "f"(x), "f"(y));
    return r;
}
__device__ __forceinline__ unsigned long long ffma2(unsigned long long a,
                                                    unsigned long long b,
                                                    unsigned long long c) {
    unsigned long long d;
    asm("fma.rn.f32x2 %0, %1, %2, %3;" : "=l"(d) : "l"(a), "l"(b), "l"(c));
    return d;
}
__device__ __forceinline__ float2 unpack2(unsigned long long v) {
    float2 f;
    asm("mov.b64 {%0, %1}, %2;" : "=f"(f.x), "=f"(f.y) : "l"(v));
    return f;
}

// ---------------- fused layer GEMM (+head on layer 2) ----------------
// 128 threads/block, one row per thread, f32x2 packed accumulators.
// layer==1: h1 = relu(x@root + sum_r agg[r]@W[r] + b) -> pool slice 3
// layer==2: logits = relu(...) @ Wc + bc -> out   (h2 never materialized)
__global__ __launch_bounds__(128) void rgcn_gemm_k(
    const float* __restrict__ x,
    const float* __restrict__ Wrel,
    const float* __restrict__ root,
    const float* __restrict__ bias,
    const float* __restrict__ Wc,
    const float* __restrict__ bc,
    float* __restrict__ outHead,
    int n, int layer)
{
    __shared__ __align__(16) float Ws[HH * HH];
    __shared__ float Wcs[HH * CC];
    __shared__ float bcs[CC];
    int tid = threadIdx.x;
    int row = blockIdx.x * 128 + tid;
    int crow = row < n ? row : 0;

    if (layer == 2) {
        for (int i = tid; i < HH * CC; i += 128) Wcs[i] = Wc[i];
        if (tid < CC) bcs[tid] = bc[tid];
    }

    unsigned long long acc[32];
    {
        const float2* b2 = (const float2*)bias;
        #pragma unroll
        for (int j = 0; j < 32; j++) { float2 b = b2[j]; acc[j] = pack2two(b.x, b.y); }
    }

    const float* xin = (layer == 1) ? x : (g_pool + 3 * SLICE);

    for (int m = 0; m < 4; m++) {
        const float* W = (m == 0) ? root : (Wrel + (size_t)(m - 1) * HH * HH);
        __syncthreads();
        {
            const float4* w4 = (const float4*)W;
            float4* s4 = (float4*)Ws;
            for (int i = tid; i < HH * HH / 4; i += 128) s4[i] = w4[i];
        }
        __syncthreads();

        const float* in = (m == 0) ? xin : (g_pool + (size_t)(m - 1) * SLICE);
        const float4* x4 = (const float4*)(in + (size_t)crow * HH);

        #pragma unroll 4
        for (int k4 = 0; k4 < 16; k4++) {
            float4 v = x4[k4];
            #define GSTEP(E, KK)                                                   \
            {                                                                      \
                unsigned long long p = pack2(E);                                   \
                const ulonglong2* wr = (const ulonglong2*)&Ws[(4 * k4 + KK) * HH]; \
                _Pragma("unroll")                                                  \
                for (int j = 0; j < 16; j++) {                                     \
                    ulonglong2 w2 = wr[j];                                         \
                    acc[2 * j]     = ffma2(p, w2.x, acc[2 * j]);                   \
                    acc[2 * j + 1] = ffma2(p, w2.y, acc[2 * j + 1]);               \
                }                                                                  \
            }
            GSTEP(v.x, 0)
            GSTEP(v.y, 1)
            GSTEP(v.z, 2)
            GSTEP(v.w, 3)
            #undef GSTEP
        }
    }

    if (layer == 1) {
        if (row < n) {
            float4* o4 = (float4*)(g_pool + 3 * SLICE + (size_t)row * HH);
            #pragma unroll
            for (int j = 0; j < 16; j++) {
                float2 lo = unpack2(acc[2 * j]);
                float2 hi = unpack2(acc[2 * j + 1]);
                float a = lo.x > 0.f ? lo.x : 0.f;
                float b = lo.y > 0.f ? lo.y : 0.f;
                float c = hi.x > 0.f ? hi.x : 0.f;
                float d = hi.y > 0.f ? hi.y : 0.f;
                o4[j] = make_float4(a, b, c, d);
            }
        }
    } else {
        // fused classifier head: logits = relu(h2) @ Wc + bc
        float p[CC];
        #pragma unroll
        for (int c = 0; c < CC; c++) p[c] = bcs[c];
        #pragma unroll
        for (int j = 0; j < 32; j++) {
            float2 v = unpack2(acc[j]);
            float h0 = v.x > 0.f ? v.x : 0.f;
            float h1 = v.y > 0.f ? v.y : 0.f;
            int k0 = 2 * j;
            #pragma unroll
            for (int c = 0; c < CC; c++)
                p[c] += h0 * Wcs[k0 * CC + c] + h1 * Wcs[(k0 + 1) * CC + c];
        }
        if (row < n) {
            #pragma unroll
            for (int c = 0; c < CC; c++)
                outHead[(size_t)row * CC + c] = p[c];
        }
    }
}

// ---------------- launch ----------------
extern "C" void kernel_launch(void* const* d_in, const int* in_sizes, int n_in,
                              void* d_out, int out_size)
{
    const float* x     = (const float*)d_in[0];
    const float* W1    = (const float*)d_in[1];
    const float* root1 = (const float*)d_in[2];
    const float* b1    = (const float*)d_in[3];
    const float* W2    = (const float*)d_in[4];
    const float* root2 = (const float*)d_in[5];
    const float* b2    = (const float*)d_in[6];
    const float* Wc    = (const float*)d_in[7];
    const float* bc    = (const float*)d_in[8];
    const void*  ei    = d_in[9];
    const void*  et    = d_in[10];
    float* out = (float*)d_out;

    int n  = in_sizes[0] / HH;     // 50000
    int e  = in_sizes[10];         // 800000
    int n3 = n * RR;

    // single cooperative kernel builds the whole CSR (detect+count+scan+fill)
    {
        const int* w32 = (const int*)ei;
        void* args[] = { (void*)&w32, (void*)&ei, (void*)&et, (void*)&e, (void*)&n3 };
        cudaLaunchCooperativeKernel((const void*)csr_k,
                                    dim3(CSR_BLOCKS), dim3(CSR_THREADS),
                                    args, 0, 0);
    }

    int aggBlocks  = (n3 * 32 + 255) / 256;
    int gemmBlocks = (n + 127) / 128;

    // layer 1
    agg_k<<<aggBlocks, 256>>>(x, n, 1);
    rgcn_gemm_k<<<gemmBlocks, 128>>>(x, W1, root1, b1, Wc, bc, out, n, 1);

    // layer 2 (head fused)
    agg_k<<<aggBlocks, 256>>>(x, n, 2);
    rgcn_gemm_k<<<gemmBlocks, 128>>>(x, W2, root2, b2, Wc, bc, out, n, 2);
}